// round 5
// baseline (speedup 1.0000x reference)
#include <cuda_runtime.h>
#include <cuda_bf16.h>

// HATS constants (fixed by the problem definition)
#define KCELL   10
#define RR      3
#define SSZ     7          // 2R+1
#define NBINS   98         // 2 * S * S
#define GWW     24         // W / K
#define NCELLS  432        // (H/K)*(W/K) = 18*24
#define TAU_INV (1.0f / 1e6f)
#define DT_MAX  1e5f
#define CAP     64         // max events per (batch, cell) bucket (mean ~4.3)
#define MAXB    16         // max batch supported by scratch
#define NBLK    64         // persistent blocks (<= 148 SMs -> co-resident)
#define NTHR    256        // threads per block (8 warps)
#define WPB     8

// Scratch (device globals — zero-initialized at module load; the kernel
// self-cleans g_bcount / g_done after use, so every replay starts clean).
__device__ int    g_bcount[MAXB * NCELLS];
__device__ float4 g_bev  [MAXB * NCELLS * CAP];
__device__ int    g_bidx [MAXB * NCELLS * CAP];
__device__ int    g_done1;
__device__ int    g_done2;

// ---------------------------------------------------------------------------
// Single persistent kernel: scatter -> device-wide soft barrier -> per-cell
// pairwise accumulation with fused normalization. NBLK blocks are always
// co-resident, so the spin barrier cannot deadlock.
// ---------------------------------------------------------------------------
__global__ __launch_bounds__(NTHR, 1)
void hats_fused_kernel(const float4* __restrict__ ev,
                       const int* __restrict__ lengths,
                       float* __restrict__ out,
                       int T, int total, int nct) {
    __shared__ float4 sev [WPB][CAP];
    __shared__ int    sidx[WPB][CAP];
    __shared__ float  hist[WPB][NBINS];

    int tid  = threadIdx.x;
    int warp = tid >> 5;
    int lane = tid & 31;

    // ---- Phase 1: scatter valid events into (batch, cell) buckets ----
    for (int g = blockIdx.x * NTHR + tid; g < total; g += NBLK * NTHR) {
        int b = g / T;
        int i = g - b * T;
        if (i < lengths[b]) {
            float4 e = ev[g];
            int cell = ((int)e.y / KCELL) * GWW + ((int)e.x / KCELL);
            int gc = b * NCELLS + cell;
            int slot = atomicAdd(&g_bcount[gc], 1);
            if (slot < CAP) {
                g_bev [gc * CAP + slot] = e;
                g_bidx[gc * CAP + slot] = i;   // original index -> causality
            }
        }
    }

    // ---- Device-wide soft barrier (all NBLK blocks are resident) ----
    __threadfence();
    __syncthreads();
    if (tid == 0) {
        atomicAdd(&g_done1, 1);
        while (*(volatile int*)&g_done1 < NBLK) { }
    }
    __syncthreads();
    __threadfence();

    // ---- Phase 2: per-cell pairwise surfaces, one warp per cell ----
    for (int gc = blockIdx.x * WPB + warp; gc < nct; gc += NBLK * WPB) {
        int rawcnt = g_bcount[gc];
        if (lane == 0) g_bcount[gc] = 0;       // self-clean for next replay
        int n = rawcnt < CAP ? rawcnt : CAP;

        for (int k = lane; k < NBINS; k += 32) hist[warp][k] = 0.0f;
        for (int k = lane; k < n; k += 32) {
            sev [warp][k] = g_bev [gc * CAP + k];
            sidx[warp][k] = g_bidx[gc * CAP + k];
        }
        __syncwarp();

        int np = n * n;
        for (int p = lane; p < np; p += 32) {
            int a = p / n;                      // center event
            int c = p - a * n;                  // contributor
            if (sidx[warp][c] > sidx[warp][a]) continue;    // causal: j <= i
            float4 fa = sev[warp][a];
            float4 fb = sev[warp][c];
            float dt = fa.z - fb.z;             // >= 0 by causality + sorted t
            if (dt > DT_MAX) continue;
            int dx = (int)fb.x - (int)fa.x + RR;
            int dy = (int)fb.y - (int)fa.y + RR;
            if ((unsigned)dx < SSZ && (unsigned)dy < SSZ && fa.w == fb.w) {
                int bin = ((int)fa.w * SSZ + dy) * SSZ + dx;
                atomicAdd(&hist[warp][bin], __expf(-dt * TAU_INV));
            }
        }
        __syncwarp();

        float inv = 1.0f / fmaxf((float)rawcnt, 1.0f);
        float* obase = out + (size_t)gc * NBINS;
        for (int k = lane; k < NBINS; k += 32) obase[k] = hist[warp][k] * inv;
        __syncwarp();
    }

    // ---- Reset barrier counters for the next graph replay ----
    __syncthreads();
    if (tid == 0) {
        int r = atomicAdd(&g_done2, 1);
        if (r == NBLK - 1) {                   // last block to finish
            g_done1 = 0;
            g_done2 = 0;
            __threadfence();
        }
    }
}

// ---------------------------------------------------------------------------
// Launch
// ---------------------------------------------------------------------------
extern "C" void kernel_launch(void* const* d_in, const int* in_sizes, int n_in,
                              void* d_out, int out_size) {
    const float4* ev = (const float4*)d_in[0];  // [B, T, 4] = (x, y, t, p)
    const int* lengths = (const int*)d_in[1];   // [B]
    float* out = (float*)d_out;                 // [B, NC, 2, S, S] float32

    int B = in_sizes[1];
    int T = in_sizes[0] / (4 * B);
    int nct = B * NCELLS;
    int total = B * T;

    hats_fused_kernel<<<NBLK, NTHR>>>(ev, lengths, out, T, total, nct);
}

// round 8
// speedup vs baseline: 3.0491x; 3.0491x over previous
#include <cuda_runtime.h>
#include <cuda_bf16.h>

// HATS constants (fixed by the problem definition)
#define KCELL   10
#define RR      3
#define SSZ     7          // 2R+1
#define NBINS   98         // 2 * S * S
#define GWW     24         // W / K
#define NCELLS  432        // (H/K)*(W/K) = 18*24
#define TAU_INV (1.0f / 1e6f)
#define DT_MAX  1e5f

#define CSPLIT  16         // blocks per batch; 432 / 16 = 27 cells per block
#define CPB     27         // cells per block
#define CAP     32         // max events kept per cell (mean ~4.7, P(>=32)~1e-15)
#define NTHR    256        // 8 warps
#define WPB     8

// ---------------------------------------------------------------------------
// Single kernel, no global scratch. Block (b, s) owns cells
// [s*CPB, (s+1)*CPB) of batch b. It scans batch b's events, buckets the ones
// in its slice into shared memory, then computes each cell's pairwise
// exponentially-decayed time surface and writes the normalized histogram.
// ---------------------------------------------------------------------------
__global__ __launch_bounds__(NTHR)
void hats_onekernel(const float4* __restrict__ ev,
                    const int* __restrict__ lengths,
                    float* __restrict__ out, int T) {
    __shared__ int   scnt[CPB];
    __shared__ uint2 sbuk[CPB][CAP];   // .x = t bits, .y = packed x|y<<8|p<<16|idx<<17
    __shared__ float hist[WPB][NBINS];

    int tid  = threadIdx.x;
    int warp = tid >> 5;
    int lane = tid & 31;
    int b  = blockIdx.x / CSPLIT;
    int s  = blockIdx.x - b * CSPLIT;
    int c0 = s * CPB;                  // first cell owned by this block

    for (int k = tid; k < CPB; k += NTHR) scnt[k] = 0;
    __syncthreads();

    // ---- Phase 1: scan batch events, keep those in our cell slice ----
    int len = lengths[b];
    const float4* evb = ev + (size_t)b * T;
    #pragma unroll 4
    for (int i = tid; i < T; i += NTHR) {
        if (i >= len) break;           // valid prefix only (loop is monotone in i)
        float4 e = evb[i];
        int xi = (int)e.x, yi = (int)e.y;
        int cell = (yi / KCELL) * GWW + (xi / KCELL);
        int cl = cell - c0;
        if ((unsigned)cl < CPB) {
            int slot = atomicAdd(&scnt[cl], 1);
            if (slot < CAP) {
                uint2 v;
                v.x = __float_as_uint(e.z);
                v.y = (unsigned)xi | ((unsigned)yi << 8)
                    | ((unsigned)(int)e.w << 16) | ((unsigned)i << 17);
                sbuk[cl][slot] = v;
            }
        }
    }
    __syncthreads();

    // ---- Phase 2: per-cell pairwise surfaces, one warp per cell ----
    for (int cl = warp; cl < CPB; cl += WPB) {
        int rawcnt = scnt[cl];
        int n = rawcnt < CAP ? rawcnt : CAP;

        for (int k = lane; k < NBINS; k += 32) hist[warp][k] = 0.0f;
        __syncwarp();

        int np = n * n;
        for (int p = lane; p < np; p += 32) {
            int a = p / n;                      // center event i
            int c = p - a * n;                  // contributor j
            uint2 va = sbuk[cl][a];
            uint2 vc = sbuk[cl][c];
            if ((vc.y >> 17) > (va.y >> 17)) continue;   // causal: idx_j <= idx_i
            float dt = __uint_as_float(va.x) - __uint_as_float(vc.x);  // >= 0
            if (dt > DT_MAX) continue;
            int dx = (int)(vc.y & 0xFF)        - (int)(va.y & 0xFF)        + RR;
            int dy = (int)((vc.y >> 8) & 0xFF) - (int)((va.y >> 8) & 0xFF) + RR;
            int pa = (va.y >> 16) & 1, pc = (vc.y >> 16) & 1;
            if ((unsigned)dx < SSZ && (unsigned)dy < SSZ && pa == pc) {
                int bin = (pa * SSZ + dy) * SSZ + dx;
                atomicAdd(&hist[warp][bin], __expf(-dt * TAU_INV));
            }
        }
        __syncwarp();

        float inv = 1.0f / fmaxf((float)rawcnt, 1.0f);
        float* obase = out + (size_t)(b * NCELLS + c0 + cl) * NBINS;
        for (int k = lane; k < NBINS; k += 32) obase[k] = hist[warp][k] * inv;
        __syncwarp();
    }
}

// ---------------------------------------------------------------------------
// Launch
// ---------------------------------------------------------------------------
extern "C" void kernel_launch(void* const* d_in, const int* in_sizes, int n_in,
                              void* d_out, int out_size) {
    const float4* ev = (const float4*)d_in[0];  // [B, T, 4] = (x, y, t, p)
    const int* lengths = (const int*)d_in[1];   // [B]
    float* out = (float*)d_out;                 // [B, NC, 2, S, S] float32

    int B = in_sizes[1];
    int T = in_sizes[0] / (4 * B);

    hats_onekernel<<<B * CSPLIT, NTHR>>>(ev, lengths, out, T);
}

// round 9
// speedup vs baseline: 4.5625x; 1.4963x over previous
#include <cuda_runtime.h>
#include <cuda_bf16.h>

// HATS constants (fixed by the problem definition)
#define KCELL   10
#define RR      3
#define SSZ     7          // 2R+1
#define NBINS   98         // 2 * S * S
#define GWW     24         // W / K
#define NCELLS  432        // (H/K)*(W/K) = 18*24
#define TAU_INV (1.0f / 1e6f)
#define DT_MAX  1e5f

#define CSPLIT  18         // blocks per batch; 432 / 18 = 24 cells per block
#define CPB     24         // cells per block
#define CAP     32         // max events kept per cell (mean ~4.7, P(>=32)~1e-15)
#define NTHR    512        // 16 warps
#define WPB     16
#define UNROLL  4          // event loads in flight per thread per outer iter

// ---------------------------------------------------------------------------
// Single kernel, no global scratch. Block (b, s) owns cells
// [s*CPB, (s+1)*CPB) of batch b. Phase 1 scans batch b's events with fully
// unrolled UNCONDITIONAL loads (only the insert is predicated on validity),
// bucketing slice events into shared memory. Phase 2: one warp per cell does
// the n^2 causal pair loop and writes the normalized histogram.
// ---------------------------------------------------------------------------
__global__ __launch_bounds__(NTHR)
void hats_onekernel(const float4* __restrict__ ev,
                    const int* __restrict__ lengths,
                    float* __restrict__ out, int T) {
    __shared__ int   scnt[CPB];
    __shared__ uint2 sbuk[CPB][CAP];   // .x = t bits, .y = x|y<<8|p<<16|idx<<17
    __shared__ float hist[WPB][NBINS];

    int tid  = threadIdx.x;
    int warp = tid >> 5;
    int lane = tid & 31;
    int b  = blockIdx.x / CSPLIT;
    int s  = blockIdx.x - b * CSPLIT;
    int c0 = s * CPB;                  // first cell owned by this block

    for (int k = tid; k < CPB; k += NTHR) scnt[k] = 0;

    int len = lengths[b];              // overlaps with the event loads below
    const float4* evb = ev + (size_t)b * T;
    __syncthreads();

    // ---- Phase 1: scan all T events, batched independent loads ----
    for (int i0 = 0; i0 < T; i0 += NTHR * UNROLL) {
        float4 e[UNROLL];
        int    idx[UNROLL];
        #pragma unroll
        for (int k = 0; k < UNROLL; k++) {
            idx[k] = i0 + k * NTHR + tid;
            if (idx[k] < T) e[k] = evb[idx[k]];   // unconditional on validity
        }
        #pragma unroll
        for (int k = 0; k < UNROLL; k++) {
            int i = idx[k];
            if (i >= len) continue;               // validity gate (insert only)
            int xi = (int)e[k].x, yi = (int)e[k].y;
            int cl = (yi / KCELL) * GWW + (xi / KCELL) - c0;
            if ((unsigned)cl < CPB) {
                int slot = atomicAdd(&scnt[cl], 1);
                if (slot < CAP) {
                    uint2 v;
                    v.x = __float_as_uint(e[k].z);
                    v.y = (unsigned)xi | ((unsigned)yi << 8)
                        | ((unsigned)(int)e[k].w << 16) | ((unsigned)i << 17);
                    sbuk[cl][slot] = v;
                }
            }
        }
    }
    __syncthreads();

    // ---- Phase 2: per-cell pairwise surfaces, one warp per cell ----
    for (int cl = warp; cl < CPB; cl += WPB) {
        int rawcnt = scnt[cl];
        int n = rawcnt < CAP ? rawcnt : CAP;

        for (int k = lane; k < NBINS; k += 32) hist[warp][k] = 0.0f;
        __syncwarp();

        int np = n * n;
        for (int p = lane; p < np; p += 32) {
            int a = p / n;                      // center event i
            int c = p - a * n;                  // contributor j
            uint2 va = sbuk[cl][a];
            uint2 vc = sbuk[cl][c];
            if ((vc.y >> 17) > (va.y >> 17)) continue;   // causal: idx_j <= idx_i
            float dt = __uint_as_float(va.x) - __uint_as_float(vc.x);  // >= 0
            if (dt > DT_MAX) continue;
            int dx = (int)(vc.y & 0xFF)        - (int)(va.y & 0xFF)        + RR;
            int dy = (int)((vc.y >> 8) & 0xFF) - (int)((va.y >> 8) & 0xFF) + RR;
            int pa = (va.y >> 16) & 1, pc = (vc.y >> 16) & 1;
            if ((unsigned)dx < SSZ && (unsigned)dy < SSZ && pa == pc) {
                int bin = (pa * SSZ + dy) * SSZ + dx;
                atomicAdd(&hist[warp][bin], __expf(-dt * TAU_INV));
            }
        }
        __syncwarp();

        float inv = 1.0f / fmaxf((float)rawcnt, 1.0f);
        float* obase = out + (size_t)(b * NCELLS + c0 + cl) * NBINS;
        for (int k = lane; k < NBINS; k += 32) obase[k] = hist[warp][k] * inv;
        __syncwarp();
    }
}

// ---------------------------------------------------------------------------
// Launch
// ---------------------------------------------------------------------------
extern "C" void kernel_launch(void* const* d_in, const int* in_sizes, int n_in,
                              void* d_out, int out_size) {
    const float4* ev = (const float4*)d_in[0];  // [B, T, 4] = (x, y, t, p)
    const int* lengths = (const int*)d_in[1];   // [B]
    float* out = (float*)d_out;                 // [B, NC, 2, S, S] float32

    int B = in_sizes[1];
    int T = in_sizes[0] / (4 * B);

    hats_onekernel<<<B * CSPLIT, NTHR>>>(ev, lengths, out, T);
}

// round 10
// speedup vs baseline: 4.5793x; 1.0037x over previous
#include <cuda_runtime.h>
#include <cuda_bf16.h>

// HATS constants (fixed by the problem definition)
#define KCELL   10
#define RR      3
#define SSZ     7          // 2R+1
#define NBINS   98         // 2 * S * S
#define GWW     24         // W / K
#define NCELLS  432        // (H/K)*(W/K) = 18*24
#define TAU_INV (1.0f / 1e6f)
#define DT_MAX  1e5f

#define CSPLIT  18         // blocks per batch; 432 / 18 = 24 cells per block
#define CPB     24         // cells per block
#define CAP     32         // max events kept per cell (mean ~4.7, P(>=32)~1e-15)
#define NTHR    512        // 16 warps
#define WPB     16
#define UNROLL  4          // event loads in flight per thread per outer iter

// Exact v/10 for 0 <= v < 256 (x < 240, y < 180): one IMAD + one SHF.
__device__ __forceinline__ int div10(int v) { return (v * 205) >> 11; }

// ---------------------------------------------------------------------------
// Single kernel, no global scratch. Block (b, s) owns cells
// [s*CPB, (s+1)*CPB) of batch b. Phase 1 scans batch b's events with fully
// unrolled unconditional loads and a ~10-instruction filter; only slice
// events take the insert path. Phase 2: one warp per cell does the n^2
// causal pair loop and writes the normalized histogram.
// ---------------------------------------------------------------------------
__global__ __launch_bounds__(NTHR)
void hats_onekernel(const float4* __restrict__ ev,
                    const int* __restrict__ lengths,
                    float* __restrict__ out, int T) {
    __shared__ int   scnt[CPB];
    __shared__ uint2 sbuk[CPB][CAP];   // .x = t bits, .y = x|y<<8|p<<16|idx<<17
    __shared__ float hist[WPB][NBINS];

    int tid  = threadIdx.x;
    int warp = tid >> 5;
    int lane = tid & 31;
    int b  = blockIdx.x / CSPLIT;
    int s  = blockIdx.x - b * CSPLIT;
    int c0 = s * CPB;                  // first cell owned by this block

    for (int k = tid; k < CPB; k += NTHR) scnt[k] = 0;

    int len = lengths[b];              // overlaps with the event loads below
    const float4* evb = ev + (size_t)b * T;
    __syncthreads();

    // ---- Phase 1: scan all T events, batched independent loads ----
    for (int i0 = 0; i0 < T; i0 += NTHR * UNROLL) {
        float4 e[UNROLL];
        int    idx[UNROLL];
        #pragma unroll
        for (int k = 0; k < UNROLL; k++) {
            idx[k] = i0 + k * NTHR + tid;
            if (idx[k] < T) e[k] = evb[idx[k]];   // unconditional on validity
        }
        #pragma unroll
        for (int k = 0; k < UNROLL; k++) {
            int i = idx[k];
            int xi = (int)e[k].x, yi = (int)e[k].y;
            int cl = div10(yi) * GWW + div10(xi) - c0;   // cheap filter
            if ((unsigned)cl < CPB && i < len) {         // rare insert path
                int slot = atomicAdd(&scnt[cl], 1);
                if (slot < CAP) {
                    uint2 v;
                    v.x = __float_as_uint(e[k].z);
                    v.y = (unsigned)xi | ((unsigned)yi << 8)
                        | ((unsigned)(int)e[k].w << 16) | ((unsigned)i << 17);
                    sbuk[cl][slot] = v;
                }
            }
        }
    }
    __syncthreads();

    // ---- Phase 2: per-cell pairwise surfaces, one warp per cell ----
    for (int cl = warp; cl < CPB; cl += WPB) {
        int rawcnt = scnt[cl];
        int n = rawcnt < CAP ? rawcnt : CAP;

        for (int k = lane; k < NBINS; k += 32) hist[warp][k] = 0.0f;
        __syncwarp();

        int np = n * n;
        float rn = n > 0 ? __frcp_rn((float)n) : 0.0f;
        for (int p = lane; p < np; p += 32) {
            int a = __float2int_rd((float)p * rn);       // ~ p / n
            if (a * n > p) a--;                          // fixup (rcp rounding)
            else if ((a + 1) * n <= p) a++;
            int c = p - a * n;                           // contributor j
            uint2 va = sbuk[cl][a];
            uint2 vc = sbuk[cl][c];
            if ((vc.y >> 17) > (va.y >> 17)) continue;   // causal: idx_j <= idx_i
            float dt = __uint_as_float(va.x) - __uint_as_float(vc.x);  // >= 0
            if (dt > DT_MAX) continue;
            int dx = (int)(vc.y & 0xFF)        - (int)(va.y & 0xFF)        + RR;
            int dy = (int)((vc.y >> 8) & 0xFF) - (int)((va.y >> 8) & 0xFF) + RR;
            int pa = (va.y >> 16) & 1, pc = (vc.y >> 16) & 1;
            if ((unsigned)dx < SSZ && (unsigned)dy < SSZ && pa == pc) {
                int bin = (pa * SSZ + dy) * SSZ + dx;
                atomicAdd(&hist[warp][bin], __expf(-dt * TAU_INV));
            }
        }
        __syncwarp();

        float inv = 1.0f / fmaxf((float)rawcnt, 1.0f);
        float* obase = out + (size_t)(b * NCELLS + c0 + cl) * NBINS;
        for (int k = lane; k < NBINS; k += 32) obase[k] = hist[warp][k] * inv;
        __syncwarp();
    }
}

// ---------------------------------------------------------------------------
// Launch
// ---------------------------------------------------------------------------
extern "C" void kernel_launch(void* const* d_in, const int* in_sizes, int n_in,
                              void* d_out, int out_size) {
    const float4* ev = (const float4*)d_in[0];  // [B, T, 4] = (x, y, t, p)
    const int* lengths = (const int*)d_in[1];   // [B]
    float* out = (float*)d_out;                 // [B, NC, 2, S, S] float32

    int B = in_sizes[1];
    int T = in_sizes[0] / (4 * B);

    hats_onekernel<<<B * CSPLIT, NTHR>>>(ev, lengths, out, T);
}